// round 1
// baseline (speedup 1.0000x reference)
#include <cuda_runtime.h>
#include <cuda_bf16.h>
#include <math.h>

// ---------------- problem constants ----------------
#define BATCH 4
#define NPTS  4096
#define BN    (BATCH*NPTS)          // 16384
#define DP    128
#define DM    256
#define KNN_K 16
#define BNK   (BN*KNN_K)            // 262144
#define INV_SCALE 0.0625f           // 1/sqrt(256)

// ---------------- device scratch ----------------
__device__ int   g_knn[BN * KNN_K];
__device__ float g_x1 [BN * DM];
__device__ float g_x2 [BN * DM];
__device__ float g_q  [BN * DM];
__device__ float g_kf [BN * DM];
__device__ float g_vf [BN * DM];
__device__ float g_res[BN * DM];
__device__ float g_bufA[(size_t)BNK * DM];   // t1 -> h -> a
__device__ float g_bufC[(size_t)BNK * DM];   // t2
__device__ float g_pe  [(size_t)BNK * DM];   // pos_enc

// ---------------- KNN: top-32 (even ranks) over 4096 candidates ----------------
__global__ __launch_bounds__(128) void knn_kernel(
    const float* __restrict__ xyz1, const float* __restrict__ xyz2,
    int* __restrict__ knn)
{
    __shared__ float sp[NPTS * 3];      // 48KB, xyz2 for this batch
    int b = blockIdx.y;
    const float* p2 = xyz2 + (size_t)b * NPTS * 3;
    for (int i = threadIdx.x; i < NPTS * 3; i += 128) sp[i] = p2[i];
    __syncthreads();

    int n = blockIdx.x * 128 + threadIdx.x;      // local point index within batch
    const float* qp = xyz1 + ((size_t)b * NPTS + n) * 3;
    float qx = qp[0], qy = qp[1], qz = qp[2];
    float qn = qx*qx + qy*qy + qz*qz;

    float bd[32];
    int   bi[32];
#pragma unroll
    for (int i = 0; i < 32; i++) { bd[i] = 3.4e38f; bi[i] = -1; }

    for (int j = 0; j < NPTS; j++) {
        float px = sp[3*j], py = sp[3*j+1], pz = sp[3*j+2];
        float pn  = px*px + py*py + pz*pz;
        float dot = qx*px + qy*py + qz*pz;
        float d   = qn + pn - 2.0f * dot;     // same expansion as reference
        if (d < bd[31]) {
            int p = 31;
            while (p > 0 && d < bd[p-1]) {    // strict < keeps stable tie order
                bd[p] = bd[p-1]; bi[p] = bi[p-1]; --p;
            }
            bd[p] = d; bi[p] = j;
        }
    }
    int* o = knn + ((size_t)b * NPTS + n) * KNN_K;
#pragma unroll
    for (int k = 0; k < KNN_K; k++) o[k] = bi[2*k];   // idx2k[..., ::2]
}

// ---------------- generic fp32 GEMM: C = act(A@W + bias) (+ extra) ----------------
// A: MxK row-major, W: KxN row-major, C: MxN. M%128==0, N%128==0, K%16==0.
__global__ __launch_bounds__(256) void sgemm_kernel(
    int M, int N, int K,
    const float* __restrict__ A, const float* __restrict__ W,
    const float* __restrict__ bias, const float* __restrict__ extra,
    float* __restrict__ C, int reluFlag)
{
    constexpr int BM = 128, BN_ = 128, BK = 16;
    __shared__ float As[BK][BM + 4];
    __shared__ float Ws[BK][BN_ + 4];

    int tid = threadIdx.x;
    int bm = blockIdx.y * BM;
    int bn = blockIdx.x * BN_;
    int tr = (tid >> 4) << 3;       // 0..120 step 8
    int tc = (tid & 15) << 3;       // 0..120 step 8

    float acc[8][8];
#pragma unroll
    for (int i = 0; i < 8; i++)
#pragma unroll
        for (int j = 0; j < 8; j++) acc[i][j] = 0.0f;

    int aRow = tid >> 2;            // 0..63
    int aCol = (tid & 3) << 2;      // 0,4,8,12
    int wRow = tid >> 5;            // 0..7
    int wCol = (tid & 31) << 2;     // 0..124

    const float* Abase = A + (size_t)bm * K;

    for (int k0 = 0; k0 < K; k0 += BK) {
#pragma unroll
        for (int i = 0; i < 2; i++) {
            int r = aRow + i * 64;
            float4 v = *reinterpret_cast<const float4*>(Abase + (size_t)r * K + k0 + aCol);
            As[aCol+0][r] = v.x; As[aCol+1][r] = v.y;
            As[aCol+2][r] = v.z; As[aCol+3][r] = v.w;
        }
#pragma unroll
        for (int i = 0; i < 2; i++) {
            int r = wRow + i * 8;
            float4 v = *reinterpret_cast<const float4*>(W + (size_t)(k0 + r) * N + bn + wCol);
            *reinterpret_cast<float4*>(&Ws[r][wCol]) = v;
        }
        __syncthreads();
#pragma unroll
        for (int kk = 0; kk < BK; kk++) {
            float ra[8], rb[8];
#pragma unroll
            for (int i = 0; i < 8; i++) ra[i] = As[kk][tr + i];
#pragma unroll
            for (int j = 0; j < 8; j++) rb[j] = Ws[kk][tc + j];
#pragma unroll
            for (int i = 0; i < 8; i++)
#pragma unroll
                for (int j = 0; j < 8; j++)
                    acc[i][j] = fmaf(ra[i], rb[j], acc[i][j]);
        }
        __syncthreads();
    }

#pragma unroll
    for (int i = 0; i < 8; i++) {
        int row = bm + tr + i;
#pragma unroll
        for (int j0 = 0; j0 < 8; j0 += 4) {
            int col = bn + tc + j0;
            float4 v;
            v.x = acc[i][j0+0]; v.y = acc[i][j0+1];
            v.z = acc[i][j0+2]; v.w = acc[i][j0+3];
            if (bias) {
                const float4 bq = *reinterpret_cast<const float4*>(bias + col);
                v.x += bq.x; v.y += bq.y; v.z += bq.z; v.w += bq.w;
            }
            if (reluFlag) {
                v.x = fmaxf(v.x, 0.f); v.y = fmaxf(v.y, 0.f);
                v.z = fmaxf(v.z, 0.f); v.w = fmaxf(v.w, 0.f);
            }
            if (extra) {
                const float4 eq = *reinterpret_cast<const float4*>(extra + (size_t)row * N + col);
                v.x += eq.x; v.y += eq.y; v.z += eq.z; v.w += eq.w;
            }
            *reinterpret_cast<float4*>(C + (size_t)row * N + col) = v;
        }
    }
}

// ---------------- t1 = relu(rel @ Wd1 + bd1), one block per query ----------------
__global__ __launch_bounds__(256) void t1_kernel(
    const float* __restrict__ xyz1, const float* __restrict__ xyz2,
    const int* __restrict__ knn, const float* __restrict__ Wd1,
    const float* __restrict__ bd1, float* __restrict__ t1)
{
    int n = blockIdx.x;             // global query 0..16383
    int b = n >> 12;
    int c = threadIdx.x;
    __shared__ float rel[KNN_K][3];
    if (c < KNN_K * 3) {
        int k = c / 3, d = c % 3;
        int j = knn[n * KNN_K + k];
        rel[k][d] = xyz1[(size_t)n * 3 + d] - xyz2[((size_t)b * NPTS + j) * 3 + d];
    }
    __syncthreads();
    float w0 = Wd1[c], w1 = Wd1[DM + c], w2 = Wd1[2*DM + c], bb = bd1[c];
#pragma unroll
    for (int k = 0; k < KNN_K; k++) {
        float v = fmaf(rel[k][0], w0, fmaf(rel[k][1], w1, fmaf(rel[k][2], w2, bb)));
        t1[((size_t)(n * KNN_K + k)) * DM + c] = fmaxf(v, 0.0f);
    }
}

// ---------------- h = pe + q[n] - kf[knn], one block per query ----------------
__global__ __launch_bounds__(256) void h_kernel(
    const float* __restrict__ pe, const float* __restrict__ q,
    const float* __restrict__ kf, const int* __restrict__ knn,
    float* __restrict__ h)
{
    int n = blockIdx.x;
    int b = n >> 12;
    int c = threadIdx.x;
    __shared__ int sj[KNN_K];
    if (c < KNN_K) sj[c] = knn[n * KNN_K + c];
    __syncthreads();
    float qv = q[(size_t)n * DM + c];
#pragma unroll
    for (int k = 0; k < KNN_K; k++) {
        size_t r = (size_t)(n * KNN_K + k) * DM + c;
        h[r] = pe[r] + qv - kf[((size_t)b * NPTS + sj[k]) * DM + c];
    }
}

// ---- softmax over K axis (per channel) + res = sum_k attn*(v+pe), per query ----
__global__ __launch_bounds__(256) void softmax_reduce_kernel(
    const float* __restrict__ a, const float* __restrict__ pe,
    const float* __restrict__ vf, const int* __restrict__ knn,
    float* __restrict__ out_attn, float* __restrict__ res)
{
    int n = blockIdx.x;
    int b = n >> 12;
    int c = threadIdx.x;
    __shared__ int sj[KNN_K];
    if (c < KNN_K) sj[c] = knn[n * KNN_K + c];
    __syncthreads();

    float vals[KNN_K];
    float m = -3.4e38f;
#pragma unroll
    for (int k = 0; k < KNN_K; k++) {
        vals[k] = a[(size_t)(n * KNN_K + k) * DM + c];
        m = fmaxf(m, vals[k]);
    }
    float s = 0.0f;
#pragma unroll
    for (int k = 0; k < KNN_K; k++) {
        vals[k] = expf((vals[k] - m) * INV_SCALE);
        s += vals[k];
    }
    float inv = 1.0f / s;
    float r = 0.0f;
#pragma unroll
    for (int k = 0; k < KNN_K; k++) {
        float at = vals[k] * inv;
        size_t rr = (size_t)(n * KNN_K + k) * DM + c;
        out_attn[rr] = at;
        r = fmaf(at, vf[((size_t)b * NPTS + sj[k]) * DM + c] + pe[rr], r);
    }
    res[(size_t)n * DM + c] = r;
}

// ---------------- host launch ----------------
extern "C" void kernel_launch(void* const* d_in, const int* in_sizes, int n_in,
                              void* d_out, int out_size)
{
    const float* xyz1      = (const float*)d_in[0];
    const float* features1 = (const float*)d_in[1];
    const float* xyz2      = (const float*)d_in[2];
    const float* features2 = (const float*)d_in[3];
    const float* W_fc1     = (const float*)d_in[4];
    const float* b_fc1     = (const float*)d_in[5];
    const float* W_fc2     = (const float*)d_in[6];
    const float* b_fc2     = (const float*)d_in[7];
    const float* Wd1       = (const float*)d_in[8];
    const float* bd1       = (const float*)d_in[9];
    const float* Wd2       = (const float*)d_in[10];
    const float* bd2       = (const float*)d_in[11];
    const float* Wg1       = (const float*)d_in[12];
    const float* bg1       = (const float*)d_in[13];
    const float* Wg2       = (const float*)d_in[14];
    const float* bg2       = (const float*)d_in[15];
    const float* Wq        = (const float*)d_in[16];
    const float* Wk        = (const float*)d_in[17];
    const float* Wv        = (const float*)d_in[18];

    float* out_res  = (float*)d_out;                       // (4,4096,128)
    float* out_attn = (float*)d_out + (size_t)BN * DP;     // (4,4096,16,256)

    int*   p_knn;  cudaGetSymbolAddress((void**)&p_knn,  g_knn);
    float* p_x1;   cudaGetSymbolAddress((void**)&p_x1,   g_x1);
    float* p_x2;   cudaGetSymbolAddress((void**)&p_x2,   g_x2);
    float* p_q;    cudaGetSymbolAddress((void**)&p_q,    g_q);
    float* p_kf;   cudaGetSymbolAddress((void**)&p_kf,   g_kf);
    float* p_vf;   cudaGetSymbolAddress((void**)&p_vf,   g_vf);
    float* p_res;  cudaGetSymbolAddress((void**)&p_res,  g_res);
    float* p_bufA; cudaGetSymbolAddress((void**)&p_bufA, g_bufA);
    float* p_bufC; cudaGetSymbolAddress((void**)&p_bufC, g_bufC);
    float* p_pe;   cudaGetSymbolAddress((void**)&p_pe,   g_pe);

    // 1) KNN indices
    knn_kernel<<<dim3(NPTS / 128, BATCH), 128>>>(xyz1, xyz2, p_knn);

    // 2) shared-MLP fc1 on both feature sets
    sgemm_kernel<<<dim3(DM/128, BN/128), 256>>>(BN, DM, DP, features1, W_fc1, b_fc1, nullptr, p_x1, 0);
    sgemm_kernel<<<dim3(DM/128, BN/128), 256>>>(BN, DM, DP, features2, W_fc1, b_fc1, nullptr, p_x2, 0);

    // 3) q / k / v projections
    sgemm_kernel<<<dim3(DM/128, BN/128), 256>>>(BN, DM, DM, p_x1, Wq, nullptr, nullptr, p_q,  0);
    sgemm_kernel<<<dim3(DM/128, BN/128), 256>>>(BN, DM, DM, p_x2, Wk, nullptr, nullptr, p_kf, 0);
    sgemm_kernel<<<dim3(DM/128, BN/128), 256>>>(BN, DM, DM, p_x2, Wv, nullptr, nullptr, p_vf, 0);

    // 4) pos_enc layer 1 (K=3, custom), then layer 2 GEMM
    t1_kernel<<<BN, 256>>>(xyz1, xyz2, p_knn, Wd1, bd1, p_bufA);
    sgemm_kernel<<<dim3(DM/128, BNK/128), 256>>>(BNK, DM, DM, p_bufA, Wd2, bd2, nullptr, p_pe, 0);

    // 5) h = q - k_gather + pe  (reuses bufA)
    h_kernel<<<BN, 256>>>(p_pe, p_q, p_kf, p_knn, p_bufA);

    // 6) attention MLP: t2 = relu(h@Wg1+bg1); a = t2@Wg2+bg2 (back into bufA)
    sgemm_kernel<<<dim3(DM/128, BNK/128), 256>>>(BNK, DM, DM, p_bufA, Wg1, bg1, nullptr, p_bufC, 1);
    sgemm_kernel<<<dim3(DM/128, BNK/128), 256>>>(BNK, DM, DM, p_bufC, Wg2, bg2, nullptr, p_bufA, 0);

    // 7) softmax over K + weighted reduce (writes attn output directly)
    softmax_reduce_kernel<<<BN, 256>>>(p_bufA, p_pe, p_vf, p_knn, out_attn, p_res);

    // 8) final projection + residual (writes res output)
    sgemm_kernel<<<dim3(DP/128, BN/128), 256>>>(BN, DP, DM, p_res, W_fc2, b_fc2, features1, out_res, 0);
}

// round 3
// speedup vs baseline: 1.7242x; 1.7242x over previous
#include <cuda_runtime.h>
#include <cuda_bf16.h>
#include <cstdint>
#include <math.h>

// ---------------- problem constants ----------------
#define BATCH 4
#define NPTS  4096
#define BN    (BATCH*NPTS)          // 16384
#define DP    128
#define DM    256
#define KNN_K 16
#define BNK   (BN*KNN_K)            // 262144
#define INV_SCALE 0.0625f           // 1/sqrt(256)

// ---------------- device scratch ----------------
__device__ int   g_knn[BN * KNN_K];
__device__ float g_x1 [BN * DM];
__device__ float g_x2 [BN * DM];
__device__ float g_q  [BN * DM];
__device__ float g_kf [BN * DM];
__device__ float g_vf [BN * DM];
__device__ float g_res[BN * DM];
__device__ float g_bufA[(size_t)BNK * DM];   // t1 -> h -> a
__device__ float g_bufC[(size_t)BNK * DM];   // t2
__device__ float g_pe  [(size_t)BNK * DM];   // pos_enc
// transposed weights, [N rows][K cols] K-major
__device__ float g_wt_fc1[DM * DP];   // 256 x 128
__device__ float g_wt_fc2[DP * DM];   // 128 x 256
__device__ float g_wt_d2 [DM * DM];
__device__ float g_wt_g1 [DM * DM];
__device__ float g_wt_g2 [DM * DM];
__device__ float g_wt_q  [DM * DM];
__device__ float g_wt_k  [DM * DM];
__device__ float g_wt_v  [DM * DM];

// ---------------- PTX helpers ----------------
__device__ __forceinline__ uint32_t smem_u32(const void* p) {
    uint32_t a;
    asm("{ .reg .u64 t; cvta.to.shared.u64 t, %1; cvt.u32.u64 %0, t; }" : "=r"(a) : "l"(p));
    return a;
}

#define CP16(dst, src) \
    asm volatile("cp.async.cg.shared.global [%0], [%1], 16;" :: "r"(dst), "l"(src))
#define CP_COMMIT() asm volatile("cp.async.commit_group;" ::: "memory")
template <int N> __device__ __forceinline__ void cp_wait() {
    asm volatile("cp.async.wait_group %0;" :: "n"(N) : "memory");
}

__device__ __forceinline__ uint32_t f2tf32(float x) {
    uint32_t r;
    asm("cvt.rna.tf32.f32 %0, %1;" : "=r"(r) : "f"(x));
    return r;
}

__device__ __forceinline__ void mma_tf32(float* d, const uint32_t* a, const uint32_t* b) {
    asm volatile(
        "mma.sync.aligned.m16n8k8.row.col.f32.tf32.tf32.f32 "
        "{%0,%1,%2,%3},{%4,%5,%6,%7},{%8,%9},{%0,%1,%2,%3};"
        : "+f"(d[0]), "+f"(d[1]), "+f"(d[2]), "+f"(d[3])
        : "r"(a[0]), "r"(a[1]), "r"(a[2]), "r"(a[3]), "r"(b[0]), "r"(b[1]));
}

// ---------------- weight transpose: W (KxN) -> WT (NxK) ----------------
__global__ void transpose_kernel(const float* __restrict__ W, float* __restrict__ WT,
                                 int K, int N)
{
    __shared__ float t[32][33];
    int bx = blockIdx.x * 32, by = blockIdx.y * 32;
    int tx = threadIdx.x, ty = threadIdx.y;      // 32 x 8
#pragma unroll
    for (int i = 0; i < 32; i += 8)
        t[ty + i][tx] = W[(size_t)(by + ty + i) * N + bx + tx];
    __syncthreads();
#pragma unroll
    for (int i = 0; i < 32; i += 8)
        WT[(size_t)(bx + ty + i) * K + by + tx] = t[tx][ty + i];
}

// ---------------- tf32 mma.sync GEMM: C = act(A @ WT^T + bias) (+extra) ----------------
// A: MxK row-major fp32. WT: NxK row-major. C: MxN. M%128==0, N%128==0, K%32==0.
// smem per stage: A 128x32 pad->stride 36 floats (18432B) + B same. 2 stages.
#define LDSTRIDE 36
#define A_WORDS  (128 * LDSTRIDE)            // 4608 floats
#define STAGE_WORDS (2 * A_WORDS)            // 9216 floats
#define GEMM_SMEM (2 * STAGE_WORDS * 4)      // 73728 bytes

__global__ __launch_bounds__(256, 2) void gemm_mma_kernel(
    int M, int N, int K,
    const float* __restrict__ A, const float* __restrict__ WT,
    const float* __restrict__ bias, const float* __restrict__ extra,
    float* __restrict__ C, int reluFlag)
{
    extern __shared__ __align__(16) float sm[];
    const uint32_t sbase = smem_u32(sm);

    const int tid = threadIdx.x;
    const int bm = blockIdx.y * 128, bn = blockIdx.x * 128;
    const int lane = tid & 31, gid = lane >> 2, tig = lane & 3;
    const int w = tid >> 5, wm = w & 1, wn = w >> 1;     // warp 2x4 grid

    float acc[4][4][4];
#pragma unroll
    for (int i = 0; i < 4; i++)
#pragma unroll
        for (int j = 0; j < 4; j++)
#pragma unroll
            for (int r = 0; r < 4; r++) acc[i][j][r] = 0.0f;

    const int Cn = K >> 5;                 // K / 32
    const int cprow = tid >> 3;            // 0..31 row base for copies (x4 blocks)
    const int cpcol = (tid & 7) * 4;       // float offset (16B chunk)

    // issue stage copy for K-chunk c into buffer (c&1)
    auto issue = [&](int c) {
        uint32_t as = sbase + (uint32_t)(c & 1) * (STAGE_WORDS * 4);
        uint32_t bs = as + A_WORDS * 4;
        const float* Ag = A  + (size_t)bm * K + (size_t)c * 32;
        const float* Bg = WT + (size_t)bn * K + (size_t)c * 32;
#pragma unroll
        for (int t = 0; t < 4; t++) {
            int row = cprow + t * 32;
            uint32_t off = (uint32_t)row * (LDSTRIDE * 4) + cpcol * 4;
            CP16(as + off, Ag + (size_t)row * K + cpcol);
            CP16(bs + off, Bg + (size_t)row * K + cpcol);
        }
        CP_COMMIT();
    };

    issue(0);
    for (int c = 0; c < Cn; c++) {
        if (c + 1 < Cn) { issue(c + 1); cp_wait<1>(); }
        else            { cp_wait<0>(); }
        __syncthreads();

        const float* Ap = sm + (c & 1) * STAGE_WORDS;
        const float* Bp = Ap + A_WORDS;
        const float* Aw = Ap + (wm * 64 + gid) * LDSTRIDE;   // warp's A row base
        const float* Bw = Bp + (wn * 32 + gid) * LDSTRIDE;   // warp's B col base

#pragma unroll
        for (int kk = 0; kk < 4; kk++) {
            const int kb = kk * 8 + tig;
            uint32_t af[4][4];
#pragma unroll
            for (int i = 0; i < 4; i++) {
                const float* p = Aw + i * (16 * LDSTRIDE);
                af[i][0] = f2tf32(p[kb]);
                af[i][1] = f2tf32(p[8 * LDSTRIDE + kb]);
                af[i][2] = f2tf32(p[kb + 4]);
                af[i][3] = f2tf32(p[8 * LDSTRIDE + kb + 4]);
            }
            uint32_t bf[4][2];
#pragma unroll
            for (int j = 0; j < 4; j++) {
                const float* p = Bw + j * (8 * LDSTRIDE);
                bf[j][0] = f2tf32(p[kb]);
                bf[j][1] = f2tf32(p[kb + 4]);
            }
#pragma unroll
            for (int i = 0; i < 4; i++)
#pragma unroll
                for (int j = 0; j < 4; j++)
                    mma_tf32(acc[i][j], af[i], bf[j]);
        }
        __syncthreads();
    }

    // epilogue: float2 stores, fused bias/relu/residual
    const int rowbase = bm + wm * 64;
    const int colbase = bn + wn * 32 + tig * 2;
#pragma unroll
    for (int i = 0; i < 4; i++) {
        int r0 = rowbase + i * 16 + gid;
#pragma unroll
        for (int j = 0; j < 4; j++) {
            int col = colbase + j * 8;
            float2 v0 = make_float2(acc[i][j][0], acc[i][j][1]);
            float2 v1 = make_float2(acc[i][j][2], acc[i][j][3]);
            if (bias) {
                float2 bb = *reinterpret_cast<const float2*>(bias + col);
                v0.x += bb.x; v0.y += bb.y; v1.x += bb.x; v1.y += bb.y;
            }
            if (reluFlag) {
                v0.x = fmaxf(v0.x, 0.f); v0.y = fmaxf(v0.y, 0.f);
                v1.x = fmaxf(v1.x, 0.f); v1.y = fmaxf(v1.y, 0.f);
            }
            if (extra) {
                float2 e0 = *reinterpret_cast<const float2*>(extra + (size_t)r0 * N + col);
                float2 e1 = *reinterpret_cast<const float2*>(extra + (size_t)(r0 + 8) * N + col);
                v0.x += e0.x; v0.y += e0.y; v1.x += e1.x; v1.y += e1.y;
            }
            *reinterpret_cast<float2*>(C + (size_t)r0 * N + col) = v0;
            *reinterpret_cast<float2*>(C + (size_t)(r0 + 8) * N + col) = v1;
        }
    }
}

// ---------------- KNN: top-32 (even ranks) over 4096 candidates ----------------
__global__ __launch_bounds__(128) void knn_kernel(
    const float* __restrict__ xyz1, const float* __restrict__ xyz2,
    int* __restrict__ knn)
{
    __shared__ float sp[NPTS * 3];
    int b = blockIdx.y;
    const float* p2 = xyz2 + (size_t)b * NPTS * 3;
    for (int i = threadIdx.x; i < NPTS * 3; i += 128) sp[i] = p2[i];
    __syncthreads();

    int n = blockIdx.x * 128 + threadIdx.x;
    const float* qp = xyz1 + ((size_t)b * NPTS + n) * 3;
    float qx = qp[0], qy = qp[1], qz = qp[2];
    float qn = qx*qx + qy*qy + qz*qz;

    float bd[32];
    int   bi[32];
#pragma unroll
    for (int i = 0; i < 32; i++) { bd[i] = 3.4e38f; bi[i] = -1; }

    for (int j = 0; j < NPTS; j++) {
        float px = sp[3*j], py = sp[3*j+1], pz = sp[3*j+2];
        float pn  = px*px + py*py + pz*pz;
        float dot = qx*px + qy*py + qz*pz;
        float d   = qn + pn - 2.0f * dot;
        if (d < bd[31]) {
            int p = 31;
            while (p > 0 && d < bd[p-1]) {
                bd[p] = bd[p-1]; bi[p] = bi[p-1]; --p;
            }
            bd[p] = d; bi[p] = j;
        }
    }
    int* o = knn + ((size_t)b * NPTS + n) * KNN_K;
#pragma unroll
    for (int k = 0; k < KNN_K; k++) o[k] = bi[2*k];
}

// ---------------- t1 = relu(rel @ Wd1 + bd1) ----------------
__global__ __launch_bounds__(256) void t1_kernel(
    const float* __restrict__ xyz1, const float* __restrict__ xyz2,
    const int* __restrict__ knn, const float* __restrict__ Wd1,
    const float* __restrict__ bd1, float* __restrict__ t1)
{
    int n = blockIdx.x;
    int b = n >> 12;
    int c = threadIdx.x;
    __shared__ float rel[KNN_K][3];
    if (c < KNN_K * 3) {
        int k = c / 3, d = c % 3;
        int j = knn[n * KNN_K + k];
        rel[k][d] = xyz1[(size_t)n * 3 + d] - xyz2[((size_t)b * NPTS + j) * 3 + d];
    }
    __syncthreads();
    float w0 = Wd1[c], w1 = Wd1[DM + c], w2 = Wd1[2*DM + c], bb = bd1[c];
#pragma unroll
    for (int k = 0; k < KNN_K; k++) {
        float v = fmaf(rel[k][0], w0, fmaf(rel[k][1], w1, fmaf(rel[k][2], w2, bb)));
        t1[((size_t)(n * KNN_K + k)) * DM + c] = fmaxf(v, 0.0f);
    }
}

// ---------------- h = pe + q[n] - kf[knn] ----------------
__global__ __launch_bounds__(256) void h_kernel(
    const float* __restrict__ pe, const float* __restrict__ q,
    const float* __restrict__ kf, const int* __restrict__ knn,
    float* __restrict__ h)
{
    int n = blockIdx.x;
    int b = n >> 12;
    int c = threadIdx.x;
    __shared__ int sj[KNN_K];
    if (c < KNN_K) sj[c] = knn[n * KNN_K + c];
    __syncthreads();
    float qv = q[(size_t)n * DM + c];
#pragma unroll
    for (int k = 0; k < KNN_K; k++) {
        size_t r = (size_t)(n * KNN_K + k) * DM + c;
        h[r] = pe[r] + qv - kf[((size_t)b * NPTS + sj[k]) * DM + c];
    }
}

// ---- softmax over K + res = sum_k attn*(v+pe) ----
__global__ __launch_bounds__(256) void softmax_reduce_kernel(
    const float* __restrict__ a, const float* __restrict__ pe,
    const float* __restrict__ vf, const int* __restrict__ knn,
    float* __restrict__ out_attn, float* __restrict__ res)
{
    int n = blockIdx.x;
    int b = n >> 12;
    int c = threadIdx.x;
    __shared__ int sj[KNN_K];
    if (c < KNN_K) sj[c] = knn[n * KNN_K + c];
    __syncthreads();

    float vals[KNN_K];
    float m = -3.4e38f;
#pragma unroll
    for (int k = 0; k < KNN_K; k++) {
        vals[k] = a[(size_t)(n * KNN_K + k) * DM + c];
        m = fmaxf(m, vals[k]);
    }
    float s = 0.0f;
#pragma unroll
    for (int k = 0; k < KNN_K; k++) {
        vals[k] = expf((vals[k] - m) * INV_SCALE);
        s += vals[k];
    }
    float inv = 1.0f / s;
    float r = 0.0f;
#pragma unroll
    for (int k = 0; k < KNN_K; k++) {
        float at = vals[k] * inv;
        size_t rr = (size_t)(n * KNN_K + k) * DM + c;
        out_attn[rr] = at;
        r = fmaf(at, vf[((size_t)b * NPTS + sj[k]) * DM + c] + pe[rr], r);
    }
    res[(size_t)n * DM + c] = r;
}

// ---------------- host launch ----------------
static void launch_gemm(int M, int N, int K, const float* A, const float* WT,
                        const float* bias, const float* extra, float* C, int relu)
{
    gemm_mma_kernel<<<dim3(N / 128, M / 128), 256, GEMM_SMEM>>>(M, N, K, A, WT, bias, extra, C, relu);
}

extern "C" void kernel_launch(void* const* d_in, const int* in_sizes, int n_in,
                              void* d_out, int out_size)
{
    const float* xyz1      = (const float*)d_in[0];
    const float* features1 = (const float*)d_in[1];
    const float* xyz2      = (const float*)d_in[2];
    const float* features2 = (const float*)d_in[3];
    const float* W_fc1     = (const float*)d_in[4];
    const float* b_fc1     = (const float*)d_in[5];
    const float* W_fc2     = (const float*)d_in[6];
    const float* b_fc2     = (const float*)d_in[7];
    const float* Wd1       = (const float*)d_in[8];
    const float* bd1       = (const float*)d_in[9];
    const float* Wd2       = (const float*)d_in[10];
    const float* bd2       = (const float*)d_in[11];
    const float* Wg1       = (const float*)d_in[12];
    const float* bg1       = (const float*)d_in[13];
    const float* Wg2       = (const float*)d_in[14];
    const float* bg2       = (const float*)d_in[15];
    const float* Wq        = (const float*)d_in[16];
    const float* Wk        = (const float*)d_in[17];
    const float* Wv        = (const float*)d_in[18];

    float* out_res  = (float*)d_out;
    float* out_attn = (float*)d_out + (size_t)BN * DP;

    int*   p_knn;  cudaGetSymbolAddress((void**)&p_knn,  g_knn);
    float* p_x1;   cudaGetSymbolAddress((void**)&p_x1,   g_x1);
    float* p_x2;   cudaGetSymbolAddress((void**)&p_x2,   g_x2);
    float* p_q;    cudaGetSymbolAddress((void**)&p_q,    g_q);
    float* p_kf;   cudaGetSymbolAddress((void**)&p_kf,   g_kf);
    float* p_vf;   cudaGetSymbolAddress((void**)&p_vf,   g_vf);
    float* p_res;  cudaGetSymbolAddress((void**)&p_res,  g_res);
    float* p_bufA; cudaGetSymbolAddress((void**)&p_bufA, g_bufA);
    float* p_bufC; cudaGetSymbolAddress((void**)&p_bufC, g_bufC);
    float* p_pe;   cudaGetSymbolAddress((void**)&p_pe,   g_pe);
    float* w_fc1;  cudaGetSymbolAddress((void**)&w_fc1,  g_wt_fc1);
    float* w_fc2;  cudaGetSymbolAddress((void**)&w_fc2,  g_wt_fc2);
    float* w_d2;   cudaGetSymbolAddress((void**)&w_d2,   g_wt_d2);
    float* w_g1;   cudaGetSymbolAddress((void**)&w_g1,   g_wt_g1);
    float* w_g2;   cudaGetSymbolAddress((void**)&w_g2,   g_wt_g2);
    float* w_q;    cudaGetSymbolAddress((void**)&w_q,    g_wt_q);
    float* w_k;    cudaGetSymbolAddress((void**)&w_k,    g_wt_k);
    float* w_v;    cudaGetSymbolAddress((void**)&w_v,    g_wt_v);

    cudaFuncSetAttribute(gemm_mma_kernel, cudaFuncAttributeMaxDynamicSharedMemorySize, GEMM_SMEM);

    dim3 tb(32, 8);
    // W (KxN) -> WT (NxK)
    transpose_kernel<<<dim3(DM/32, DP/32), tb>>>(W_fc1, w_fc1, DP, DM);
    transpose_kernel<<<dim3(DP/32, DM/32), tb>>>(W_fc2, w_fc2, DM, DP);
    transpose_kernel<<<dim3(DM/32, DM/32), tb>>>(Wd2,  w_d2, DM, DM);
    transpose_kernel<<<dim3(DM/32, DM/32), tb>>>(Wg1,  w_g1, DM, DM);
    transpose_kernel<<<dim3(DM/32, DM/32), tb>>>(Wg2,  w_g2, DM, DM);
    transpose_kernel<<<dim3(DM/32, DM/32), tb>>>(Wq,   w_q,  DM, DM);
    transpose_kernel<<<dim3(DM/32, DM/32), tb>>>(Wk,   w_k,  DM, DM);
    transpose_kernel<<<dim3(DM/32, DM/32), tb>>>(Wv,   w_v,  DM, DM);

    // 1) KNN indices
    knn_kernel<<<dim3(NPTS / 128, BATCH), 128>>>(xyz1, xyz2, p_knn);

    // 2) shared-MLP fc1 on both feature sets
    launch_gemm(BN, DM, DP, features1, w_fc1, b_fc1, nullptr, p_x1, 0);
    launch_gemm(BN, DM, DP, features2, w_fc1, b_fc1, nullptr, p_x2, 0);

    // 3) q / k / v projections
    launch_gemm(BN, DM, DM, p_x1, w_q, nullptr, nullptr, p_q,  0);
    launch_gemm(BN, DM, DM, p_x2, w_k, nullptr, nullptr, p_kf, 0);
    launch_gemm(BN, DM, DM, p_x2, w_v, nullptr, nullptr, p_vf, 0);

    // 4) pos_enc layer 1 (K=3, custom), then layer 2 GEMM
    t1_kernel<<<BN, 256>>>(xyz1, xyz2, p_knn, Wd1, bd1, p_bufA);
    launch_gemm(BNK, DM, DM, p_bufA, w_d2, bd2, nullptr, p_pe, 0);

    // 5) h = q - k_gather + pe
    h_kernel<<<BN, 256>>>(p_pe, p_q, p_kf, p_knn, p_bufA);

    // 6) attention MLP
    launch_gemm(BNK, DM, DM, p_bufA, w_g1, bg1, nullptr, p_bufC, 1);
    launch_gemm(BNK, DM, DM, p_bufC, w_g2, bg2, nullptr, p_bufA, 0);

    // 7) softmax over K + weighted reduce
    softmax_reduce_kernel<<<BN, 256>>>(p_bufA, p_pe, p_vf, p_knn, out_attn, p_res);

    // 8) final projection + residual
    launch_gemm(BN, DP, DM, p_res, w_fc2, b_fc2, features1, out_res, 0);
}